// round 1
// baseline (speedup 1.0000x reference)
#include <cuda_runtime.h>
#include <math.h>

// Problem shape constants
#define Bb 4
#define Nn 1024
#define Dd 512
#define Hh 8
#define DH 64
#define BN 4096          // B*N
#define BHc 32           // B*H
#define FD 132           // feature row stride in global scratch
#define FS 133           // feature row stride in smem (conflict-free)

#define Z_ELEMS (4*1024*512)   // 2097152, attn starts after this in d_out

// ---------------- device scratch (static, no allocations) ----------------
__device__ float sc_qkvx[(size_t)BN * 1536];
__device__ float sc_qkvv[(size_t)BN * 1024];
__device__ float sc_F[(size_t)BHc * Nn * FD];
__device__ float sc_G[(size_t)BHc * Nn * FD];
__device__ float sc_vqs[BHc * Nn];
__device__ float sc_vks[BHc * Nn];
__device__ float sc_C2[(size_t)Nn * Nn];
__device__ float sc_C3[(size_t)Nn * Nn];
__device__ unsigned char sc_code[(size_t)Nn * Nn];

// ---------------- NT GEMM: C[M,Ncols] = A[M,512] @ W[Ncols,512]^T + bias ----------------
__global__ __launch_bounds__(256) void gemm_nt_kernel(
    const float* __restrict__ A, const float* __restrict__ W,
    const float* __restrict__ bias, float* __restrict__ C, int Ncols)
{
    __shared__ float As[16][65];
    __shared__ float Ws[16][65];
    const int m0 = blockIdx.y * 64, n0 = blockIdx.x * 64;
    const int t = threadIdx.x;
    const int tx = t & 15, ty = t >> 4;
    float acc[4][4];
#pragma unroll
    for (int i = 0; i < 4; i++)
#pragma unroll
        for (int j = 0; j < 4; j++) acc[i][j] = 0.f;

    for (int k0 = 0; k0 < 512; k0 += 16) {
#pragma unroll
        for (int r = 0; r < 4; r++) {
            int m = ty + r * 16;
            As[tx][m] = A[(size_t)(m0 + m) * 512 + k0 + tx];
            Ws[tx][m] = W[(size_t)(n0 + m) * 512 + k0 + tx];
        }
        __syncthreads();
#pragma unroll
        for (int kk = 0; kk < 16; kk++) {
            float a[4], b[4];
#pragma unroll
            for (int i = 0; i < 4; i++) a[i] = As[kk][ty * 4 + i];
#pragma unroll
            for (int j = 0; j < 4; j++) b[j] = Ws[kk][tx * 4 + j];
#pragma unroll
            for (int i = 0; i < 4; i++)
#pragma unroll
                for (int j = 0; j < 4; j++) acc[i][j] += a[i] * b[j];
        }
        __syncthreads();
    }
#pragma unroll
    for (int i = 0; i < 4; i++) {
        int row = m0 + ty * 4 + i;
#pragma unroll
        for (int j = 0; j < 4; j++) {
            int col = n0 + tx * 4 + j;
            C[(size_t)row * Ncols + col] = acc[i][j] + bias[col];
        }
    }
}

// ---------------- NN GEMM: C = A @ B, all 1024x1024 ----------------
__global__ __launch_bounds__(256) void gemm_nn_kernel(
    const float* __restrict__ A, const float* __restrict__ Bm, float* __restrict__ C)
{
    __shared__ float As[16][65];
    __shared__ float Bs[16][65];
    const int m0 = blockIdx.y * 64, n0 = blockIdx.x * 64;
    const int t = threadIdx.x;
    const int tx = t & 15, ty = t >> 4;
    float acc[4][4];
#pragma unroll
    for (int i = 0; i < 4; i++)
#pragma unroll
        for (int j = 0; j < 4; j++) acc[i][j] = 0.f;

    for (int k0 = 0; k0 < 1024; k0 += 16) {
#pragma unroll
        for (int r = 0; r < 4; r++) {
            int m = ty + r * 16;
            As[tx][m] = A[(size_t)(m0 + m) * 1024 + k0 + tx];
        }
#pragma unroll
        for (int r = 0; r < 4; r++) {
            int kk = (t >> 6) + r * 4;
            int n = t & 63;
            Bs[kk][n] = Bm[(size_t)(k0 + kk) * 1024 + n0 + n];
        }
        __syncthreads();
#pragma unroll
        for (int kk = 0; kk < 16; kk++) {
            float a[4], b[4];
#pragma unroll
            for (int i = 0; i < 4; i++) a[i] = As[kk][ty * 4 + i];
#pragma unroll
            for (int j = 0; j < 4; j++) b[j] = Bs[kk][tx * 4 + j];
#pragma unroll
            for (int i = 0; i < 4; i++)
#pragma unroll
                for (int j = 0; j < 4; j++) acc[i][j] += a[i] * b[j];
        }
        __syncthreads();
    }
#pragma unroll
    for (int i = 0; i < 4; i++) {
        int row = m0 + ty * 4 + i;
#pragma unroll
        for (int j = 0; j < 4; j++)
            C[(size_t)row * 1024 + n0 + tx * 4 + j] = acc[i][j];
    }
}

// ---------------- feature preprocessing ----------------
// one warp per (b,h,n): bound tangent, exp_map0, fused feature rows
__global__ __launch_bounds__(256) void pre_kernel(const float* __restrict__ tau)
{
    const int w = blockIdx.x * 8 + (threadIdx.x >> 5);
    const int lane = threadIdx.x & 31;
    const int bh = w >> 10, n = w & 1023;
    const int b = bh >> 3, h = bh & 7;
    const size_t bn = (size_t)b * Nn + n;
    const float* px = sc_qkvx + bn * 1536 + h * 64;
    const float* pv = sc_qkvv + bn * 1024 + h * 64;

    float q0 = px[lane],        q1 = px[32 + lane];
    float k0 = px[512 + lane],  k1 = px[512 + 32 + lane];
    float vq0 = pv[lane],       vq1 = pv[32 + lane];
    float vk0 = pv[512 + lane], vk1 = pv[512 + 32 + lane];

    const float tc = fmaxf(tau[h], 0.001f);
    const float itau = 1.0f / tc;

    // q: bound + exp map
    float sq = q0 * q0 + q1 * q1;
#pragma unroll
    for (int o = 16; o; o >>= 1) sq += __shfl_xor_sync(0xffffffffu, sq, o);
    float nrm = sqrtf(fmaxf(sq, 1e-7f));
    float fac = fminf(3.0f / nrm, 1.0f);
    float qb0 = q0 * fac, qb1 = q1 * fac;
    float sqb = qb0 * qb0 + qb1 * qb1;
#pragma unroll
    for (int o = 16; o; o >>= 1) sqb += __shfl_xor_sync(0xffffffffu, sqb, o);
    float nq = sqrtf(fmaxf(sqb, 1e-14f));
    float shq = sinhf(nq) / nq, chq = coshf(nq);

    // k: bound + exp map
    float sk = k0 * k0 + k1 * k1;
#pragma unroll
    for (int o = 16; o; o >>= 1) sk += __shfl_xor_sync(0xffffffffu, sk, o);
    float nrk = sqrtf(fmaxf(sk, 1e-7f));
    float fkk = fminf(3.0f / nrk, 1.0f);
    float kb0 = k0 * fkk, kb1 = k1 * fkk;
    float skb = kb0 * kb0 + kb1 * kb1;
#pragma unroll
    for (int o = 16; o; o >>= 1) skb += __shfl_xor_sync(0xffffffffu, skb, o);
    float nk = sqrtf(fmaxf(skb, 1e-14f));
    float shk = sinhf(nk) / nk, chk = coshf(nk);

    // v norms
    float svq = vq0 * vq0 + vq1 * vq1;
#pragma unroll
    for (int o = 16; o; o >>= 1) svq += __shfl_xor_sync(0xffffffffu, svq, o);
    float svk = vk0 * vk0 + vk1 * vk1;
#pragma unroll
    for (int o = 16; o; o >>= 1) svk += __shfl_xor_sync(0xffffffffu, svk, o);

    const size_t fo = ((size_t)bh * Nn + n) * FD;
    sc_F[fo + lane]      = qb0 * shq * itau;
    sc_F[fo + 32 + lane] = qb1 * shq * itau;
    sc_F[fo + 64 + lane] = 2.0f * vq0;
    sc_F[fo + 96 + lane] = 2.0f * vq1;
    sc_G[fo + lane]      = kb0 * shk;
    sc_G[fo + 32 + lane] = kb1 * shk;
    sc_G[fo + 64 + lane] = vk0;
    sc_G[fo + 96 + lane] = vk1;
    if (lane == 0) {
        sc_F[fo + 128] = -chq * itau;
        sc_G[fo + 128] = chk;
        sc_vqs[bh * Nn + n] = svq;
        sc_vks[bh * Nn + n] = svk;
    }
}

// ---------------- topo mask packing ----------------
__global__ __launch_bounds__(256) void code_kernel(const float* __restrict__ A)
{
    const int idx = blockIdx.x * 256 + threadIdx.x;
    const int i = idx >> 10, j = idx & 1023;
    unsigned char c = 0;
    if (i != j) {
        if (A[idx] > 0.f) c |= 1;
        if (sc_C2[idx] > 0.f) c |= 2;
        if (sc_C3[idx] > 0.f) c |= 4;
    }
    sc_code[idx] = c;
}

// ---------------- fused attention: scores + softmax + attn out + z ----------------
#define ATTN_SMEM_FLOATS (16*1024 + 16*FS + 128*FS + 16 + 128 + 8)

__global__ __launch_bounds__(256) void attn_kernel(
    const float* __restrict__ tau, const float* __restrict__ gamma,
    float* __restrict__ out)
{
    extern __shared__ float sm[];
    float* S   = sm;                   // 16 x 1024 scores -> probs
    float* Ft  = S + 16 * 1024;        // 16 x FS
    float* Gt  = Ft + 16 * FS;         // 128 x FS
    float* vqs = Gt + 128 * FS;        // 16
    float* vks = vqs + 16;             // 128
    float* lut = vks + 128;            // 8

    const int bh = blockIdx.x, it = blockIdx.y;
    const int i0 = it * 16;
    const int h = bh & 7, b = bh >> 3;
    const int t = threadIdx.x;
    const float itau = 1.0f / fmaxf(tau[h], 0.001f);

    for (int idx = t; idx < 16 * 129; idx += 256) {
        int r = idx / 129, c = idx - r * 129;
        Ft[r * FS + c] = sc_F[((size_t)bh * Nn + i0 + r) * FD + c];
    }
    if (t < 16) vqs[t] = sc_vqs[bh * Nn + i0 + t];
    if (t < 8)
        lut[t] = gamma[h * 3 + 0] * (float)(t & 1)
               + gamma[h * 3 + 1] * (float)((t >> 1) & 1)
               + gamma[h * 3 + 2] * (float)((t >> 2) & 1);

    const int tig = t >> 6;   // 0..3 -> 4 i rows each
    const int tj  = t & 63;   // 0..63 -> 2 j cols each

    for (int jc = 0; jc < 8; jc++) {
        const int j0 = jc * 128;
        __syncthreads();   // protect Gt (and first-iter Ft/lut) ordering
        for (int idx = t; idx < 128 * 129; idx += 256) {
            int r = idx / 129, c = idx - r * 129;
            Gt[r * FS + c] = sc_G[((size_t)bh * Nn + j0 + r) * FD + c];
        }
        if (t < 128) vks[t] = sc_vks[bh * Nn + j0 + t];
        __syncthreads();

        float a1[4][2], a2[4][2];
#pragma unroll
        for (int p = 0; p < 4; p++) { a1[p][0]=a1[p][1]=a2[p][0]=a2[p][1]=0.f; }
        const float* g0p = Gt + (2 * tj) * FS;
        const float* g1p = g0p + FS;
#pragma unroll 4
        for (int kk = 0; kk < 64; kk++) {
            float g0 = g0p[kk], g1 = g1p[kk];
#pragma unroll
            for (int p = 0; p < 4; p++) {
                float f = Ft[(tig * 4 + p) * FS + kk];
                a1[p][0] += f * g0; a1[p][1] += f * g1;
            }
        }
#pragma unroll 4
        for (int kk = 64; kk < 128; kk++) {
            float g0 = g0p[kk], g1 = g1p[kk];
#pragma unroll
            for (int p = 0; p < 4; p++) {
                float f = Ft[(tig * 4 + p) * FS + kk];
                a2[p][0] += f * g0; a2[p][1] += f * g1;
            }
        }
        const float g0t = g0p[128], g1t = g1p[128];
#pragma unroll
        for (int p = 0; p < 4; p++) {
            const int i = tig * 4 + p;
            const float ft = Ft[i * FS + 128];
            const float geo0 = itau + a1[p][0] + ft * g0t;
            const float geo1 = itau + a1[p][1] + ft * g1t;
#pragma unroll
            for (int jj = 0; jj < 2; jj++) {
                const int jr = 2 * tj + jj;
                const int jg = j0 + jr;
                const float geo = jj ? geo1 : geo0;
                const float kin = fminf((jj ? a2[p][1] : a2[p][0]) - vqs[i] - vks[jr], 0.0f);
                const unsigned char c = sc_code[(size_t)(i0 + i) * Nn + jg];
                S[i * 1024 + jg] = geo + kin + lut[c];
            }
        }
    }
    __syncthreads();

    // row softmax (warp w handles rows 2w, 2w+1), write attn, keep probs in S
    const int w = t >> 5, lane = t & 31;
    float* attn_out = out + (size_t)Z_ELEMS;
    for (int rr = 0; rr < 2; rr++) {
        const int i = w * 2 + rr;
        float* row = S + i * 1024;
        float m = -3.4e38f;
        for (int j = lane; j < 1024; j += 32) m = fmaxf(m, row[j]);
#pragma unroll
        for (int o = 16; o; o >>= 1) m = fmaxf(m, __shfl_xor_sync(0xffffffffu, m, o));
        float ssum = 0.f;
        for (int j = lane; j < 1024; j += 32) {
            float e = expf(row[j] - m);
            row[j] = e; ssum += e;
        }
#pragma unroll
        for (int o = 16; o; o >>= 1) ssum += __shfl_xor_sync(0xffffffffu, ssum, o);
        const float inv = 1.0f / ssum;
        float* ao = attn_out + ((size_t)bh * Nn + i0 + i) * Nn;
        for (int j = lane; j < 1024; j += 32) {
            float p = row[j] * inv;
            row[j] = p; ao[j] = p;
        }
    }
    __syncthreads();

    // z = P @ V ; V[j][d] = qkvx[(b*N+j)*1536 + 1024 + h*64 + d]
    const int d = t & 63, ig = t >> 6;
    const float* Vp = sc_qkvx + (size_t)b * Nn * 1536 + 1024 + h * 64 + d;
    float acc[4] = {0.f, 0.f, 0.f, 0.f};
#pragma unroll 4
    for (int j = 0; j < 1024; j++) {
        float v = Vp[(size_t)j * 1536];
#pragma unroll
        for (int p = 0; p < 4; p++) acc[p] += S[(ig + 4 * p) * 1024 + j] * v;
    }
#pragma unroll
    for (int p = 0; p < 4; p++) {
        const int i = ig + 4 * p;
        out[((size_t)b * Nn + i0 + i) * Dd + h * 64 + d] = acc[p];
    }
}

// ---------------- launch ----------------
extern "C" void kernel_launch(void* const* d_in, const int* in_sizes, int n_in,
                              void* d_out, int out_size)
{
    const float* x     = (const float*)d_in[0];
    const float* v     = (const float*)d_in[1];
    const float* Atopo = (const float*)d_in[2];
    const float* W     = (const float*)d_in[3];
    const float* bias  = (const float*)d_in[4];
    const float* tau   = (const float*)d_in[5];
    const float* gamma = (const float*)d_in[6];
    float* out = (float*)d_out;

    float *p_qkvx, *p_qkvv, *p_C2, *p_C3;
    cudaGetSymbolAddress((void**)&p_qkvx, sc_qkvx);
    cudaGetSymbolAddress((void**)&p_qkvv, sc_qkvv);
    cudaGetSymbolAddress((void**)&p_C2, sc_C2);
    cudaGetSymbolAddress((void**)&p_C3, sc_C3);

    const int attn_smem = ATTN_SMEM_FLOATS * 4;
    cudaFuncSetAttribute(attn_kernel, cudaFuncAttributeMaxDynamicSharedMemorySize, attn_smem);

    // QKV projections (fp32)
    gemm_nt_kernel<<<dim3(24, 64), 256>>>(x, W, bias, p_qkvx, 1536);
    gemm_nt_kernel<<<dim3(16, 64), 256>>>(v, W, bias, p_qkvv, 1024);
    // feature construction
    pre_kernel<<<4096, 256>>>(tau);
    // topo: A^2, A^3, packed masks
    gemm_nn_kernel<<<dim3(16, 16), 256>>>(Atopo, Atopo, p_C2);
    gemm_nn_kernel<<<dim3(16, 16), 256>>>(p_C2, Atopo, p_C3);
    code_kernel<<<4096, 256>>>(Atopo);
    // fused attention
    attn_kernel<<<dim3(32, 64), 256, attn_smem>>>(tau, gamma, out);
}

// round 2
// speedup vs baseline: 2.9868x; 2.9868x over previous
#include <cuda_runtime.h>
#include <math.h>

#define Bb 4
#define Nn 1024
#define Dd 512
#define Hh 8
#define BN 4096
#define BHc 32
#define FD 132

#define Z_ELEMS (4*1024*512)

// ---------------- device scratch ----------------
__device__ float sc_qkvx[(size_t)BN * 1536];
__device__ float sc_qkvv[(size_t)BN * 1024];
__device__ float sc_F[(size_t)BHc * Nn * FD];
__device__ float sc_G[(size_t)BHc * Nn * FD];
__device__ float sc_vqs[BHc * Nn];
__device__ float sc_vks[BHc * Nn];
__device__ unsigned sc_Ab[Nn * 32];
__device__ unsigned sc_A2b[Nn * 32];
__device__ unsigned sc_A3b[Nn * 32];
__device__ unsigned char sc_code[(size_t)Nn * Nn];

// ---------------- QKV projection: C[M,ld] = A[M,512] @ W[*,512]^T + bias ----------------
// 128x128 tile, 8x8 per thread, kchunk=8
__global__ __launch_bounds__(256) void qkv_kernel(
    const float* __restrict__ A, const float* __restrict__ W,
    const float* __restrict__ bias, float* __restrict__ C, int ldc)
{
    __shared__ float As[8][132];
    __shared__ float Ws[8][132];
    const int m0 = blockIdx.y * 128, n0 = blockIdx.x * 128;
    const int t = threadIdx.x;
    const int ty = t >> 4, tx = t & 15;
    const int ri = ty * 8, rj = tx * 8;
    const int lr = t >> 1, lk = (t & 1) * 4;

    float acc[8][8];
#pragma unroll
    for (int i = 0; i < 8; i++)
#pragma unroll
        for (int j = 0; j < 8; j++) acc[i][j] = 0.f;

    const float* Ap = A + (size_t)(m0 + lr) * 512 + lk;
    const float* Wp = W + (size_t)(n0 + lr) * 512 + lk;

    for (int k0 = 0; k0 < 512; k0 += 8) {
        float4 av = *(const float4*)(Ap + k0);
        float4 wv = *(const float4*)(Wp + k0);
        __syncthreads();
        As[lk + 0][lr] = av.x; As[lk + 1][lr] = av.y; As[lk + 2][lr] = av.z; As[lk + 3][lr] = av.w;
        Ws[lk + 0][lr] = wv.x; Ws[lk + 1][lr] = wv.y; Ws[lk + 2][lr] = wv.z; Ws[lk + 3][lr] = wv.w;
        __syncthreads();
#pragma unroll
        for (int kk = 0; kk < 8; kk++) {
            float4 a0 = *(const float4*)&As[kk][ri];
            float4 a1 = *(const float4*)&As[kk][ri + 4];
            float4 b0 = *(const float4*)&Ws[kk][rj];
            float4 b1 = *(const float4*)&Ws[kk][rj + 4];
            float af[8] = {a0.x,a0.y,a0.z,a0.w,a1.x,a1.y,a1.z,a1.w};
            float bf[8] = {b0.x,b0.y,b0.z,b0.w,b1.x,b1.y,b1.z,b1.w};
#pragma unroll
            for (int i = 0; i < 8; i++)
#pragma unroll
                for (int j = 0; j < 8; j++) acc[i][j] += af[i] * bf[j];
        }
    }
    float bs[8];
#pragma unroll
    for (int j = 0; j < 8; j++) bs[j] = bias[n0 + rj + j];
#pragma unroll
    for (int i = 0; i < 8; i++) {
        float* cp = C + (size_t)(m0 + ri + i) * ldc + n0 + rj;
        float4 o0 = {acc[i][0]+bs[0], acc[i][1]+bs[1], acc[i][2]+bs[2], acc[i][3]+bs[3]};
        float4 o1 = {acc[i][4]+bs[4], acc[i][5]+bs[5], acc[i][6]+bs[6], acc[i][7]+bs[7]};
        *(float4*)cp = o0; *(float4*)(cp + 4) = o1;
    }
}

// ---------------- feature preprocessing (one warp per (b,h,n)) ----------------
__global__ __launch_bounds__(256) void pre_kernel(const float* __restrict__ tau)
{
    const int w = blockIdx.x * 8 + (threadIdx.x >> 5);
    const int lane = threadIdx.x & 31;
    const int bh = w >> 10, n = w & 1023;
    const int b = bh >> 3, h = bh & 7;
    const size_t bn = (size_t)b * Nn + n;
    const float* px = sc_qkvx + bn * 1536 + h * 64;
    const float* pv = sc_qkvv + bn * 1024 + h * 64;

    float q0 = px[lane],        q1 = px[32 + lane];
    float k0 = px[512 + lane],  k1 = px[512 + 32 + lane];
    float vq0 = pv[lane],       vq1 = pv[32 + lane];
    float vk0 = pv[512 + lane], vk1 = pv[512 + 32 + lane];

    const float itau = 1.0f / fmaxf(tau[h], 0.001f);

    float sq = q0*q0 + q1*q1;
#pragma unroll
    for (int o = 16; o; o >>= 1) sq += __shfl_xor_sync(0xffffffffu, sq, o);
    float fac = fminf(3.0f / sqrtf(fmaxf(sq, 1e-7f)), 1.0f);
    float qb0 = q0 * fac, qb1 = q1 * fac;
    float sqb = qb0*qb0 + qb1*qb1;
#pragma unroll
    for (int o = 16; o; o >>= 1) sqb += __shfl_xor_sync(0xffffffffu, sqb, o);
    float nq = sqrtf(fmaxf(sqb, 1e-14f));
    float shq = sinhf(nq) / nq, chq = coshf(nq);

    float sk = k0*k0 + k1*k1;
#pragma unroll
    for (int o = 16; o; o >>= 1) sk += __shfl_xor_sync(0xffffffffu, sk, o);
    float fkk = fminf(3.0f / sqrtf(fmaxf(sk, 1e-7f)), 1.0f);
    float kb0 = k0 * fkk, kb1 = k1 * fkk;
    float skb = kb0*kb0 + kb1*kb1;
#pragma unroll
    for (int o = 16; o; o >>= 1) skb += __shfl_xor_sync(0xffffffffu, skb, o);
    float nk = sqrtf(fmaxf(skb, 1e-14f));
    float shk = sinhf(nk) / nk, chk = coshf(nk);

    float svq = vq0*vq0 + vq1*vq1;
#pragma unroll
    for (int o = 16; o; o >>= 1) svq += __shfl_xor_sync(0xffffffffu, svq, o);
    float svk = vk0*vk0 + vk1*vk1;
#pragma unroll
    for (int o = 16; o; o >>= 1) svk += __shfl_xor_sync(0xffffffffu, svk, o);

    const size_t fo = ((size_t)bh * Nn + n) * FD;
    sc_F[fo + lane]      = qb0 * shq * itau;
    sc_F[fo + 32 + lane] = qb1 * shq * itau;
    sc_F[fo + 64 + lane] = 2.0f * vq0;
    sc_F[fo + 96 + lane] = 2.0f * vq1;
    sc_G[fo + lane]      = kb0 * shk;
    sc_G[fo + 32 + lane] = kb1 * shk;
    sc_G[fo + 64 + lane] = vk0;
    sc_G[fo + 96 + lane] = vk1;
    if (lane == 0) {
        sc_F[fo + 128] = -chq * itau;
        sc_G[fo + 128] = chk;
        sc_vqs[bh * Nn + n] = svq;
        sc_vks[bh * Nn + n] = svk;
    }
}

// ---------------- topo: bit packing + boolean reachability ----------------
__global__ __launch_bounds__(256) void pack_kernel(const float* __restrict__ A)
{
    const int w = (blockIdx.x * 256 + threadIdx.x) >> 5;  // 0..32767
    const int lane = threadIdx.x & 31;
    const int row = w >> 5, word = w & 31;
    float v = A[(size_t)row * 1024 + word * 32 + lane];
    unsigned m = __ballot_sync(0xffffffffu, v > 0.f);
    if (lane == 0) sc_Ab[row * 32 + word] = m;
}

__global__ __launch_bounds__(256) void reach_kernel(
    const unsigned* __restrict__ src, const unsigned* __restrict__ base,
    unsigned* __restrict__ dst)
{
    const int row = (blockIdx.x * 256 + threadIdx.x) >> 5;
    const int lane = threadIdx.x & 31;
    unsigned acc = 0;
    for (int kw = 0; kw < 32; kw++) {
        unsigned w = src[row * 32 + kw];
        while (w) {
            int b = __ffs(w) - 1; w &= w - 1;
            acc |= base[(kw * 32 + b) * 32 + lane];
        }
    }
    dst[row * 32 + lane] = acc;
}

__global__ __launch_bounds__(256) void code_kernel()
{
    const int idx = blockIdx.x * 256 + threadIdx.x;
    const int i = idx >> 10, j = idx & 1023;
    const int wrd = j >> 5;
    const unsigned bit = 1u << (j & 31);
    unsigned char c = 0;
    if (i != j) {
        if (sc_Ab[i * 32 + wrd] & bit)  c |= 1;
        if (sc_A2b[i * 32 + wrd] & bit) c |= 2;
        if (sc_A3b[i * 32 + wrd] & bit) c |= 4;
    }
    sc_code[idx] = c;
}

// ---------------- fused score GEMM: kin -> clip fold -> geo -> time -> topo ----------------
__global__ __launch_bounds__(256) void score_kernel(
    const float* __restrict__ tau, const float* __restrict__ gamma,
    float* __restrict__ out)
{
    __shared__ float Fs[8][132];
    __shared__ float Gs[8][132];
    const int bh = blockIdx.x;
    const int i0 = blockIdx.y * 128, j0 = blockIdx.z * 128;
    const int h = bh & 7;
    const int t = threadIdx.x;
    const int ty = t >> 4, tx = t & 15;
    const int ri = ty * 8, rj = tx * 8;
    const int lr = t >> 1, lk = (t & 1) * 4;

    const float* Fb = sc_F + ((size_t)bh * Nn + i0) * FD;
    const float* Gb = sc_G + ((size_t)bh * Nn + j0) * FD;
    const float* Fl = Fb + (size_t)lr * FD + lk;
    const float* Gl = Gb + (size_t)lr * FD + lk;

    float acc[8][8];
#pragma unroll
    for (int i = 0; i < 8; i++)
#pragma unroll
        for (int j = 0; j < 8; j++) acc[i][j] = 0.f;

    // phase 1: kin half, k = 64..127
    for (int k0 = 64; k0 < 128; k0 += 8) {
        float4 fv = *(const float4*)(Fl + k0);
        float4 gv = *(const float4*)(Gl + k0);
        __syncthreads();
        Fs[lk+0][lr]=fv.x; Fs[lk+1][lr]=fv.y; Fs[lk+2][lr]=fv.z; Fs[lk+3][lr]=fv.w;
        Gs[lk+0][lr]=gv.x; Gs[lk+1][lr]=gv.y; Gs[lk+2][lr]=gv.z; Gs[lk+3][lr]=gv.w;
        __syncthreads();
#pragma unroll
        for (int kk = 0; kk < 8; kk++) {
            float4 a0 = *(const float4*)&Fs[kk][ri];
            float4 a1 = *(const float4*)&Fs[kk][ri + 4];
            float4 b0 = *(const float4*)&Gs[kk][rj];
            float4 b1 = *(const float4*)&Gs[kk][rj + 4];
            float af[8] = {a0.x,a0.y,a0.z,a0.w,a1.x,a1.y,a1.z,a1.w};
            float bf[8] = {b0.x,b0.y,b0.z,b0.w,b1.x,b1.y,b1.z,b1.w};
#pragma unroll
            for (int i = 0; i < 8; i++)
#pragma unroll
                for (int j = 0; j < 8; j++) acc[i][j] += af[i] * bf[j];
        }
    }

    // in-place clip fold: acc = min(acc - |vq|^2 - |vk|^2, 0) + 1/tau
    {
        const float itau = 1.0f / fmaxf(tau[h], 0.001f);
        float vq[8], vk[8];
#pragma unroll
        for (int m = 0; m < 8; m++) {
            vq[m] = sc_vqs[bh * Nn + i0 + ri + m];
            vk[m] = sc_vks[bh * Nn + j0 + rj + m];
        }
#pragma unroll
        for (int i = 0; i < 8; i++)
#pragma unroll
            for (int j = 0; j < 8; j++)
                acc[i][j] = fminf(acc[i][j] - vq[i] - vk[j], 0.f) + itau;
    }

    // phase 2: geo half, k = 0..63
    for (int k0 = 0; k0 < 64; k0 += 8) {
        float4 fv = *(const float4*)(Fl + k0);
        float4 gv = *(const float4*)(Gl + k0);
        __syncthreads();
        Fs[lk+0][lr]=fv.x; Fs[lk+1][lr]=fv.y; Fs[lk+2][lr]=fv.z; Fs[lk+3][lr]=fv.w;
        Gs[lk+0][lr]=gv.x; Gs[lk+1][lr]=gv.y; Gs[lk+2][lr]=gv.z; Gs[lk+3][lr]=gv.w;
        __syncthreads();
#pragma unroll
        for (int kk = 0; kk < 8; kk++) {
            float4 a0 = *(const float4*)&Fs[kk][ri];
            float4 a1 = *(const float4*)&Fs[kk][ri + 4];
            float4 b0 = *(const float4*)&Gs[kk][rj];
            float4 b1 = *(const float4*)&Gs[kk][rj + 4];
            float af[8] = {a0.x,a0.y,a0.z,a0.w,a1.x,a1.y,a1.z,a1.w};
            float bf[8] = {b0.x,b0.y,b0.z,b0.w,b1.x,b1.y,b1.z,b1.w};
#pragma unroll
            for (int i = 0; i < 8; i++)
#pragma unroll
                for (int j = 0; j < 8; j++) acc[i][j] += af[i] * bf[j];
        }
    }

    // time rank-1 term
    {
        float ft[8], gt[8];
#pragma unroll
        for (int m = 0; m < 8; m++) {
            ft[m] = Fb[(size_t)(ri + m) * FD + 128];
            gt[m] = Gb[(size_t)(rj + m) * FD + 128];
        }
#pragma unroll
        for (int i = 0; i < 8; i++)
#pragma unroll
            for (int j = 0; j < 8; j++) acc[i][j] += ft[i] * gt[j];
    }

    // topo lut + write raw scores into attn region of d_out
    float lut[8];
    {
        float g0 = gamma[h*3+0], g1 = gamma[h*3+1], g2 = gamma[h*3+2];
#pragma unroll
        for (int c = 0; c < 8; c++)
            lut[c] = g0 * (float)(c & 1) + g1 * (float)((c >> 1) & 1) + g2 * (float)((c >> 2) & 1);
    }
    float* attn = out + (size_t)Z_ELEMS + ((size_t)bh << 20);
#pragma unroll
    for (int i = 0; i < 8; i++) {
        const unsigned char* cp = sc_code + (size_t)(i0 + ri + i) * Nn + j0 + rj;
        uint2 cw = *(const uint2*)cp;
        float o[8];
        o[0] = acc[i][0] + lut[(cw.x      ) & 7];
        o[1] = acc[i][1] + lut[(cw.x >>  8) & 7];
        o[2] = acc[i][2] + lut[(cw.x >> 16) & 7];
        o[3] = acc[i][3] + lut[(cw.x >> 24) & 7];
        o[4] = acc[i][4] + lut[(cw.y      ) & 7];
        o[5] = acc[i][5] + lut[(cw.y >>  8) & 7];
        o[6] = acc[i][6] + lut[(cw.y >> 16) & 7];
        o[7] = acc[i][7] + lut[(cw.y >> 24) & 7];
        float* op = attn + (size_t)(i0 + ri + i) * Nn + j0 + rj;
        *(float4*)op = make_float4(o[0], o[1], o[2], o[3]);
        *(float4*)(op + 4) = make_float4(o[4], o[5], o[6], o[7]);
    }
}

// ---------------- in-place row softmax over attn region ----------------
__global__ __launch_bounds__(256) void softmax_kernel(float* __restrict__ attn)
{
    __shared__ float red[8];
    float* row = attn + (size_t)blockIdx.x * 1024;
    const int t = threadIdx.x, lane = t & 31, w = t >> 5;
    float4 v = ((const float4*)row)[t];
    float m = fmaxf(fmaxf(v.x, v.y), fmaxf(v.z, v.w));
#pragma unroll
    for (int o = 16; o; o >>= 1) m = fmaxf(m, __shfl_xor_sync(0xffffffffu, m, o));
    if (lane == 0) red[w] = m;
    __syncthreads();
    m = red[0];
#pragma unroll
    for (int i = 1; i < 8; i++) m = fmaxf(m, red[i]);
    float4 e;
    e.x = expf(v.x - m); e.y = expf(v.y - m); e.z = expf(v.z - m); e.w = expf(v.w - m);
    float s = e.x + e.y + e.z + e.w;
#pragma unroll
    for (int o = 16; o; o >>= 1) s += __shfl_xor_sync(0xffffffffu, s, o);
    __syncthreads();
    if (lane == 0) red[w] = s;
    __syncthreads();
    s = red[0];
#pragma unroll
    for (int i = 1; i < 8; i++) s += red[i];
    const float inv = 1.0f / s;
    e.x *= inv; e.y *= inv; e.z *= inv; e.w *= inv;
    ((float4*)row)[t] = e;
}

// ---------------- z = P @ V ----------------
__global__ __launch_bounds__(256) void z_kernel(
    const float* __restrict__ attn, float* __restrict__ out)
{
    __shared__ float Ps[16][132];
    __shared__ float Vs[16][68];
    const int bh = blockIdx.x, i0 = blockIdx.y * 128;
    const int b = bh >> 3, h = bh & 7;
    const int t = threadIdx.x;
    const int ty = t >> 4, tx = t & 15;
    const int ri = ty * 8, rd = tx * 4;
    const float* P = attn + ((size_t)bh << 20);
    const float* V = sc_qkvx + (size_t)b * Nn * 1536 + 1024 + h * 64;

    const int plr = t >> 1, pjo = (t & 1) * 8;   // P tile load: 128 rows x 16 j
    const int vjr = t >> 4, vdo = (t & 15) * 4;  // V tile load: 16 j x 64 d

    float acc[8][4];
#pragma unroll
    for (int i = 0; i < 8; i++)
#pragma unroll
        for (int j = 0; j < 4; j++) acc[i][j] = 0.f;

    for (int j0 = 0; j0 < 1024; j0 += 16) {
        float4 p0 = *(const float4*)(P + (size_t)(i0 + plr) * 1024 + j0 + pjo);
        float4 p1 = *(const float4*)(P + (size_t)(i0 + plr) * 1024 + j0 + pjo + 4);
        float4 vv = *(const float4*)(V + (size_t)(j0 + vjr) * 1536 + vdo);
        __syncthreads();
        Ps[pjo+0][plr]=p0.x; Ps[pjo+1][plr]=p0.y; Ps[pjo+2][plr]=p0.z; Ps[pjo+3][plr]=p0.w;
        Ps[pjo+4][plr]=p1.x; Ps[pjo+5][plr]=p1.y; Ps[pjo+6][plr]=p1.z; Ps[pjo+7][plr]=p1.w;
        *(float4*)&Vs[vjr][vdo] = vv;
        __syncthreads();
#pragma unroll
        for (int kk = 0; kk < 16; kk++) {
            float4 a0 = *(const float4*)&Ps[kk][ri];
            float4 a1 = *(const float4*)&Ps[kk][ri + 4];
            float4 bv = *(const float4*)&Vs[kk][rd];
            float af[8] = {a0.x,a0.y,a0.z,a0.w,a1.x,a1.y,a1.z,a1.w};
            float bf[4] = {bv.x,bv.y,bv.z,bv.w};
#pragma unroll
            for (int i = 0; i < 8; i++)
#pragma unroll
                for (int j = 0; j < 4; j++) acc[i][j] += af[i] * bf[j];
        }
    }
#pragma unroll
    for (int i = 0; i < 8; i++) {
        float* op = out + (size_t)(b * Nn + i0 + ri + i) * Dd + h * 64 + rd;
        *(float4*)op = make_float4(acc[i][0], acc[i][1], acc[i][2], acc[i][3]);
    }
}

// ---------------- launch ----------------
extern "C" void kernel_launch(void* const* d_in, const int* in_sizes, int n_in,
                              void* d_out, int out_size)
{
    const float* x     = (const float*)d_in[0];
    const float* v     = (const float*)d_in[1];
    const float* Atopo = (const float*)d_in[2];
    const float* W     = (const float*)d_in[3];
    const float* bias  = (const float*)d_in[4];
    const float* tau   = (const float*)d_in[5];
    const float* gamma = (const float*)d_in[6];
    float* out = (float*)d_out;

    float *p_qkvx, *p_qkvv;
    unsigned *p_Ab, *p_A2b, *p_A3b;
    cudaGetSymbolAddress((void**)&p_qkvx, sc_qkvx);
    cudaGetSymbolAddress((void**)&p_qkvv, sc_qkvv);
    cudaGetSymbolAddress((void**)&p_Ab, sc_Ab);
    cudaGetSymbolAddress((void**)&p_A2b, sc_A2b);
    cudaGetSymbolAddress((void**)&p_A3b, sc_A3b);

    // QKV projections
    qkv_kernel<<<dim3(12, 32), 256>>>(x, W, bias, p_qkvx, 1536);
    qkv_kernel<<<dim3(8, 32), 256>>>(v, W, bias, p_qkvv, 1024);
    // features
    pre_kernel<<<4096, 256>>>(tau);
    // topo bitset reachability
    pack_kernel<<<4096, 256>>>(Atopo);
    reach_kernel<<<128, 256>>>(p_Ab, p_Ab, p_A2b);
    reach_kernel<<<128, 256>>>(p_A2b, p_Ab, p_A3b);
    code_kernel<<<4096, 256>>>();
    // scores -> softmax -> z
    score_kernel<<<dim3(32, 8, 8), 256>>>(tau, gamma, out);
    softmax_kernel<<<32768, 256>>>(out + (size_t)Z_ELEMS);
    z_kernel<<<dim3(32, 8), 256>>>(out + (size_t)Z_ELEMS, out);
}

// round 4
// speedup vs baseline: 3.0203x; 1.0112x over previous
#include <cuda_runtime.h>
#include <math.h>
#include <stdint.h>

#define Bb 4
#define Nn 1024
#define Dd 512
#define Hh 8
#define BN 4096
#define BHc 32
#define FD 132

#define Z_ELEMS (4*1024*512)

// ---------------- device scratch ----------------
__device__ float sc_qkvx[(size_t)BN * 1536];
__device__ float sc_qkvv[(size_t)BN * 1024];
__device__ float sc_F[(size_t)BHc * Nn * FD];
__device__ float sc_G[(size_t)BHc * Nn * FD];
__device__ float sc_vqs[BHc * Nn];
__device__ float sc_vks[BHc * Nn];
__device__ unsigned sc_Ab[Nn * 32];
__device__ unsigned sc_A2b[Nn * 32];
__device__ unsigned sc_A3b[Nn * 32];
__device__ unsigned char sc_code[(size_t)Nn * Nn];

// ---------------- mma.sync tf32 helpers ----------------
__device__ __forceinline__ uint32_t to_tf32(float x) {
    uint32_t r;
    asm("cvt.rna.tf32.f32 %0, %1;" : "=r"(r) : "f"(x));
    return r;
}
__device__ __forceinline__ void mma8(float* c, const uint32_t* a, const uint32_t* b) {
    asm volatile(
        "mma.sync.aligned.m16n8k8.row.col.f32.tf32.tf32.f32 "
        "{%0,%1,%2,%3}, {%4,%5,%6,%7}, {%8,%9}, {%0,%1,%2,%3};"
        : "+f"(c[0]), "+f"(c[1]), "+f"(c[2]), "+f"(c[3])
        : "r"(a[0]), "r"(a[1]), "r"(a[2]), "r"(a[3]), "r"(b[0]), "r"(b[1]));
}
__device__ __forceinline__ void split_store(float v, float* ph, float* pl) {
    float hi = __uint_as_float(to_tf32(v));
    *ph = hi;
    *pl = __uint_as_float(to_tf32(v - hi));
}

// ---------------- QKV projection (SIMT fp32) ----------------
__global__ __launch_bounds__(256) void qkv_kernel(
    const float* __restrict__ A, const float* __restrict__ W,
    const float* __restrict__ bias, float* __restrict__ C, int ldc)
{
    __shared__ float As[8][132];
    __shared__ float Ws[8][132];
    const int m0 = blockIdx.y * 128, n0 = blockIdx.x * 128;
    const int t = threadIdx.x;
    const int ty = t >> 4, tx = t & 15;
    const int ri = ty * 8, rj = tx * 8;
    const int lr = t >> 1, lk = (t & 1) * 4;

    float acc[8][8];
#pragma unroll
    for (int i = 0; i < 8; i++)
#pragma unroll
        for (int j = 0; j < 8; j++) acc[i][j] = 0.f;

    const float* Ap = A + (size_t)(m0 + lr) * 512 + lk;
    const float* Wp = W + (size_t)(n0 + lr) * 512 + lk;

    for (int k0 = 0; k0 < 512; k0 += 8) {
        float4 av = *(const float4*)(Ap + k0);
        float4 wv = *(const float4*)(Wp + k0);
        __syncthreads();
        As[lk + 0][lr] = av.x; As[lk + 1][lr] = av.y; As[lk + 2][lr] = av.z; As[lk + 3][lr] = av.w;
        Ws[lk + 0][lr] = wv.x; Ws[lk + 1][lr] = wv.y; Ws[lk + 2][lr] = wv.z; Ws[lk + 3][lr] = wv.w;
        __syncthreads();
#pragma unroll
        for (int kk = 0; kk < 8; kk++) {
            float4 a0 = *(const float4*)&As[kk][ri];
            float4 a1 = *(const float4*)&As[kk][ri + 4];
            float4 b0 = *(const float4*)&Ws[kk][rj];
            float4 b1 = *(const float4*)&Ws[kk][rj + 4];
            float af[8] = {a0.x,a0.y,a0.z,a0.w,a1.x,a1.y,a1.z,a1.w};
            float bf[8] = {b0.x,b0.y,b0.z,b0.w,b1.x,b1.y,b1.z,b1.w};
#pragma unroll
            for (int i = 0; i < 8; i++)
#pragma unroll
                for (int j = 0; j < 8; j++) acc[i][j] += af[i] * bf[j];
        }
    }
    float bs[8];
#pragma unroll
    for (int j = 0; j < 8; j++) bs[j] = bias[n0 + rj + j];
#pragma unroll
    for (int i = 0; i < 8; i++) {
        float* cp = C + (size_t)(m0 + ri + i) * ldc + n0 + rj;
        float4 o0 = {acc[i][0]+bs[0], acc[i][1]+bs[1], acc[i][2]+bs[2], acc[i][3]+bs[3]};
        float4 o1 = {acc[i][4]+bs[4], acc[i][5]+bs[5], acc[i][6]+bs[6], acc[i][7]+bs[7]};
        *(float4*)cp = o0; *(float4*)(cp + 4) = o1;
    }
}

// ---------------- feature preprocessing ----------------
__global__ __launch_bounds__(256) void pre_kernel(const float* __restrict__ tau)
{
    const int w = blockIdx.x * 8 + (threadIdx.x >> 5);
    const int lane = threadIdx.x & 31;
    const int bh = w >> 10, n = w & 1023;
    const int b = bh >> 3, h = bh & 7;
    const size_t bn = (size_t)b * Nn + n;
    const float* px = sc_qkvx + bn * 1536 + h * 64;
    const float* pv = sc_qkvv + bn * 1024 + h * 64;

    float q0 = px[lane],        q1 = px[32 + lane];
    float k0 = px[512 + lane],  k1 = px[512 + 32 + lane];
    float vq0 = pv[lane],       vq1 = pv[32 + lane];
    float vk0 = pv[512 + lane], vk1 = pv[512 + 32 + lane];

    const float itau = 1.0f / fmaxf(tau[h], 0.001f);

    float sq = q0*q0 + q1*q1;
#pragma unroll
    for (int o = 16; o; o >>= 1) sq += __shfl_xor_sync(0xffffffffu, sq, o);
    float fac = fminf(3.0f / sqrtf(fmaxf(sq, 1e-7f)), 1.0f);
    float qb0 = q0 * fac, qb1 = q1 * fac;
    float sqb = qb0*qb0 + qb1*qb1;
#pragma unroll
    for (int o = 16; o; o >>= 1) sqb += __shfl_xor_sync(0xffffffffu, sqb, o);
    float nq = sqrtf(fmaxf(sqb, 1e-14f));
    float shq = sinhf(nq) / nq, chq = coshf(nq);

    float sk = k0*k0 + k1*k1;
#pragma unroll
    for (int o = 16; o; o >>= 1) sk += __shfl_xor_sync(0xffffffffu, sk, o);
    float fkk = fminf(3.0f / sqrtf(fmaxf(sk, 1e-7f)), 1.0f);
    float kb0 = k0 * fkk, kb1 = k1 * fkk;
    float skb = kb0*kb0 + kb1*kb1;
#pragma unroll
    for (int o = 16; o; o >>= 1) skb += __shfl_xor_sync(0xffffffffu, skb, o);
    float nk = sqrtf(fmaxf(skb, 1e-14f));
    float shk = sinhf(nk) / nk, chk = coshf(nk);

    float svq = vq0*vq0 + vq1*vq1;
#pragma unroll
    for (int o = 16; o; o >>= 1) svq += __shfl_xor_sync(0xffffffffu, svq, o);
    float svk = vk0*vk0 + vk1*vk1;
#pragma unroll
    for (int o = 16; o; o >>= 1) svk += __shfl_xor_sync(0xffffffffu, svk, o);

    const size_t fo = ((size_t)bh * Nn + n) * FD;
    sc_F[fo + lane]      = qb0 * shq * itau;
    sc_F[fo + 32 + lane] = qb1 * shq * itau;
    sc_F[fo + 64 + lane] = 2.0f * vq0;
    sc_F[fo + 96 + lane] = 2.0f * vq1;
    sc_G[fo + lane]      = kb0 * shk;
    sc_G[fo + 32 + lane] = kb1 * shk;
    sc_G[fo + 64 + lane] = vk0;
    sc_G[fo + 96 + lane] = vk1;
    if (lane == 0) {
        sc_F[fo + 128] = -chq * itau;
        sc_G[fo + 128] = chk;
        sc_vqs[bh * Nn + n] = svq;
        sc_vks[bh * Nn + n] = svk;
    }
}

// ---------------- topo bitsets ----------------
__global__ __launch_bounds__(256) void pack_kernel(const float* __restrict__ A)
{
    const int w = (blockIdx.x * 256 + threadIdx.x) >> 5;
    const int lane = threadIdx.x & 31;
    const int row = w >> 5, word = w & 31;
    float v = A[(size_t)row * 1024 + word * 32 + lane];
    unsigned m = __ballot_sync(0xffffffffu, v > 0.f);
    if (lane == 0) sc_Ab[row * 32 + word] = m;
}

__global__ __launch_bounds__(256) void reach_kernel(
    const unsigned* __restrict__ src, const unsigned* __restrict__ base,
    unsigned* __restrict__ dst)
{
    const int row = (blockIdx.x * 256 + threadIdx.x) >> 5;
    const int lane = threadIdx.x & 31;
    unsigned acc = 0;
    for (int kw = 0; kw < 32; kw++) {
        unsigned w = src[row * 32 + kw];
        while (w) {
            int b = __ffs(w) - 1; w &= w - 1;
            acc |= base[(kw * 32 + b) * 32 + lane];
        }
    }
    dst[row * 32 + lane] = acc;
}

__global__ __launch_bounds__(256) void code_kernel()
{
    const int idx = blockIdx.x * 256 + threadIdx.x;
    const int i = idx >> 10, j = idx & 1023;
    const int wrd = j >> 5;
    const unsigned bit = 1u << (j & 31);
    unsigned char c = 0;
    if (i != j) {
        if (sc_Ab[i * 32 + wrd] & bit)  c |= 1;
        if (sc_A2b[i * 32 + wrd] & bit) c |= 2;
        if (sc_A3b[i * 32 + wrd] & bit) c |= 4;
    }
    sc_code[idx] = c;
}

// ---------------- score kernel: tf32-3x mma.sync, kin->clip->geo fused ----------------
// smem tiles staged k-major: [k 16][row 128 + pad], stride 136 -> conflict-free frag loads
__global__ __launch_bounds__(256) void score_mma_kernel(
    const float* __restrict__ tau, const float* __restrict__ gamma,
    float* __restrict__ out)
{
    __shared__ float Fh[16][136], Fl[16][136], Gh[16][136], Gl[16][136];
    const int bh = blockIdx.x, i0 = blockIdx.y * 128, j0 = blockIdx.z * 128;
    const int h = bh & 7;
    const int t = threadIdx.x, wid = t >> 5, lane = t & 31;
    const int wm = wid & 3, wn = wid >> 2;
    const int tr = lane >> 2, tc = lane & 3;

    float acc[2][8][4];
#pragma unroll
    for (int a = 0; a < 2; a++)
#pragma unroll
        for (int b = 0; b < 8; b++)
#pragma unroll
            for (int c = 0; c < 4; c++) acc[a][b][c] = 0.f;

    const float* Fbase = sc_F + ((size_t)bh * Nn + i0) * FD;
    const float* Gbase = sc_G + ((size_t)bh * Nn + j0) * FD;
    const int srow = t >> 1, sc0 = (t & 1) * 8;

#pragma unroll
    for (int phase = 0; phase < 2; phase++) {
        const int koff = (phase == 0) ? 64 : 0;   // kin first, then geo
        for (int ch = 0; ch < 4; ch++) {
            const int kbase = koff + ch * 16;
            const float* fp = Fbase + (size_t)srow * FD + kbase + sc0;
            const float* gp = Gbase + (size_t)srow * FD + kbase + sc0;
            float4 f0 = *(const float4*)fp, f1 = *(const float4*)(fp + 4);
            float4 g0 = *(const float4*)gp, g1 = *(const float4*)(gp + 4);
            __syncthreads();
            float fa[8] = {f0.x,f0.y,f0.z,f0.w,f1.x,f1.y,f1.z,f1.w};
            float ga[8] = {g0.x,g0.y,g0.z,g0.w,g1.x,g1.y,g1.z,g1.w};
#pragma unroll
            for (int c = 0; c < 8; c++) {
                split_store(fa[c], &Fh[sc0 + c][srow], &Fl[sc0 + c][srow]);
                split_store(ga[c], &Gh[sc0 + c][srow], &Gl[sc0 + c][srow]);
            }
            __syncthreads();
#pragma unroll
            for (int s = 0; s < 2; s++) {
                const int kk = s * 8;
                uint32_t Ah[2][4], Al[2][4];
#pragma unroll
                for (int ma = 0; ma < 2; ma++) {
                    const int r = wm * 32 + ma * 16 + tr;
                    Ah[ma][0] = __float_as_uint(Fh[kk + tc][r]);
                    Ah[ma][1] = __float_as_uint(Fh[kk + tc][r + 8]);
                    Ah[ma][2] = __float_as_uint(Fh[kk + tc + 4][r]);
                    Ah[ma][3] = __float_as_uint(Fh[kk + tc + 4][r + 8]);
                    Al[ma][0] = __float_as_uint(Fl[kk + tc][r]);
                    Al[ma][1] = __float_as_uint(Fl[kk + tc][r + 8]);
                    Al[ma][2] = __float_as_uint(Fl[kk + tc + 4][r]);
                    Al[ma][3] = __float_as_uint(Fl[kk + tc + 4][r + 8]);
                }
                uint32_t Bh[8][2], Bl[8][2];
#pragma unroll
                for (int na = 0; na < 8; na++) {
                    const int n = wn * 64 + na * 8 + tr;
                    Bh[na][0] = __float_as_uint(Gh[kk + tc][n]);
                    Bh[na][1] = __float_as_uint(Gh[kk + tc + 4][n]);
                    Bl[na][0] = __float_as_uint(Gl[kk + tc][n]);
                    Bl[na][1] = __float_as_uint(Gl[kk + tc + 4][n]);
                }
#pragma unroll
                for (int ma = 0; ma < 2; ma++)
#pragma unroll
                    for (int na = 0; na < 8; na++) {
                        mma8(acc[ma][na], Ah[ma], Bh[na]);
                        mma8(acc[ma][na], Ah[ma], Bl[na]);
                        mma8(acc[ma][na], Al[ma], Bh[na]);
                    }
            }
        }
        if (phase == 0) {
            // exact kin clip fold: acc = min(acc - |vq|^2 - |vk|^2, 0)
            float vqA[2], vqB[2];
#pragma unroll
            for (int ma = 0; ma < 2; ma++) {
                vqA[ma] = sc_vqs[bh * Nn + i0 + wm * 32 + ma * 16 + tr];
                vqB[ma] = sc_vqs[bh * Nn + i0 + wm * 32 + ma * 16 + tr + 8];
            }
#pragma unroll
            for (int na = 0; na < 8; na++) {
                const int cb = wn * 64 + na * 8 + 2 * tc;
                const float vkA = sc_vks[bh * Nn + j0 + cb];
                const float vkB = sc_vks[bh * Nn + j0 + cb + 1];
#pragma unroll
                for (int ma = 0; ma < 2; ma++) {
                    acc[ma][na][0] = fminf(acc[ma][na][0] - vqA[ma] - vkA, 0.f);
                    acc[ma][na][1] = fminf(acc[ma][na][1] - vqA[ma] - vkB, 0.f);
                    acc[ma][na][2] = fminf(acc[ma][na][2] - vqB[ma] - vkA, 0.f);
                    acc[ma][na][3] = fminf(acc[ma][na][3] - vqB[ma] - vkB, 0.f);
                }
            }
        }
    }

    // epilogue: + 1/tau + time rank-1 + topo lut, write raw scores
    const float itau = 1.0f / fmaxf(tau[h], 0.001f);
    float lut[8];
    {
        const float g0 = gamma[h*3+0], g1 = gamma[h*3+1], g2 = gamma[h*3+2];
#pragma unroll
        for (int c = 0; c < 8; c++)
            lut[c] = g0 * (float)(c & 1) + g1 * (float)((c >> 1) & 1) + g2 * (float)((c >> 2) & 1);
    }
    float ftA[2], ftB[2];
#pragma unroll
    for (int ma = 0; ma < 2; ma++) {
        ftA[ma] = Fbase[(size_t)(wm * 32 + ma * 16 + tr) * FD + 128];
        ftB[ma] = Fbase[(size_t)(wm * 32 + ma * 16 + tr + 8) * FD + 128];
    }
    float gtA[8], gtB[8];
#pragma unroll
    for (int na = 0; na < 8; na++) {
        const int cb = wn * 64 + na * 8 + 2 * tc;
        gtA[na] = Gbase[(size_t)cb * FD + 128];
        gtB[na] = Gbase[(size_t)(cb + 1) * FD + 128];
    }
    float* attn = out + (size_t)Z_ELEMS + ((size_t)bh << 20);
#pragma unroll
    for (int ma = 0; ma < 2; ma++) {
        const int rA = i0 + wm * 32 + ma * 16 + tr;
        const int rB = rA + 8;
        const unsigned char* cA = sc_code + (size_t)rA * Nn + j0;
        const unsigned char* cB = sc_code + (size_t)rB * Nn + j0;
        float* oA = attn + (size_t)rA * 1024 + j0;
        float* oB = attn + (size_t)rB * 1024 + j0;
#pragma unroll
        for (int na = 0; na < 8; na++) {
            const int cb = wn * 64 + na * 8 + 2 * tc;
            const unsigned short wA = *(const unsigned short*)(cA + cb);
            const unsigned short wB = *(const unsigned short*)(cB + cb);
            float2 vA, vB;
            vA.x = acc[ma][na][0] + itau + ftA[ma] * gtA[na] + lut[wA & 7];
            vA.y = acc[ma][na][1] + itau + ftA[ma] * gtB[na] + lut[(wA >> 8) & 7];
            vB.x = acc[ma][na][2] + itau + ftB[ma] * gtA[na] + lut[wB & 7];
            vB.y = acc[ma][na][3] + itau + ftB[ma] * gtB[na] + lut[(wB >> 8) & 7];
            *(float2*)(oA + cb) = vA;
            *(float2*)(oB + cb) = vB;
        }
    }
}

// ---------------- softmax ----------------
__global__ __launch_bounds__(256) void softmax_kernel(float* __restrict__ attn)
{
    __shared__ float red[8];
    float* row = attn + (size_t)blockIdx.x * 1024;
    const int t = threadIdx.x, lane = t & 31, w = t >> 5;
    float4 v = ((const float4*)row)[t];
    float m = fmaxf(fmaxf(v.x, v.y), fmaxf(v.z, v.w));
#pragma unroll
    for (int o = 16; o; o >>= 1) m = fmaxf(m, __shfl_xor_sync(0xffffffffu, m, o));
    if (lane == 0) red[w] = m;
    __syncthreads();
    m = red[0];
#pragma unroll
    for (int i = 1; i < 8; i++) m = fmaxf(m, red[i]);
    float4 e;
    e.x = expf(v.x - m); e.y = expf(v.y - m); e.z = expf(v.z - m); e.w = expf(v.w - m);
    float s = e.x + e.y + e.z + e.w;
#pragma unroll
    for (int o = 16; o; o >>= 1) s += __shfl_xor_sync(0xffffffffu, s, o);
    __syncthreads();
    if (lane == 0) red[w] = s;
    __syncthreads();
    s = red[0];
#pragma unroll
    for (int i = 1; i < 8; i++) s += red[i];
    const float inv = 1.0f / s;
    e.x *= inv; e.y *= inv; e.z *= inv; e.w *= inv;
    ((float4*)row)[t] = e;
}

// ---------------- z = P @ V : tf32-3x mma.sync ----------------
__global__ __launch_bounds__(256) void z_mma_kernel(
    const float* __restrict__ attn, float* __restrict__ out)
{
    __shared__ float Ph[16][136], Pl[16][136], Vh[16][72], Vl[16][72];
    const int bh = blockIdx.x, i0 = blockIdx.y * 128;
    const int b = bh >> 3, h = bh & 7;
    const int t = threadIdx.x, wid = t >> 5, lane = t & 31;
    const int wm = wid & 3, wn = wid >> 2;
    const int tr = lane >> 2, tc = lane & 3;

    const float* P = attn + ((size_t)bh << 20);
    const float* V = sc_qkvx + (size_t)b * Nn * 1536 + 1024 + h * 64;

    float acc[2][4][4];
#pragma unroll
    for (int a = 0; a < 2; a++)
#pragma unroll
        for (int bb = 0; bb < 4; bb++)
#pragma unroll
            for (int c = 0; c < 4; c++) acc[a][bb][c] = 0.f;

    const int srow = t >> 1, sc0 = (t & 1) * 8;
    const int vj = t >> 4, vd0 = (t & 15) * 4;

    for (int k0 = 0; k0 < 1024; k0 += 16) {
        float4 p0 = *(const float4*)(P + (size_t)(i0 + srow) * 1024 + k0 + sc0);
        float4 p1 = *(const float4*)(P + (size_t)(i0 + srow) * 1024 + k0 + sc0 + 4);
        float4 vv = *(const float4*)(V + (size_t)(k0 + vj) * 1536 + vd0);
        __syncthreads();
        float pa[8] = {p0.x,p0.y,p0.z,p0.w,p1.x,p1.y,p1.z,p1.w};
#pragma unroll
        for (int c = 0; c < 8; c++)
            split_store(pa[c], &Ph[sc0 + c][srow], &Pl[sc0 + c][srow]);
        float va[4] = {vv.x, vv.y, vv.z, vv.w};
#pragma unroll
        for (int c = 0; c < 4; c++)
            split_store(va[c], &Vh[vj][vd0 + c], &Vl[vj][vd0 + c]);
        __syncthreads();
#pragma unroll
        for (int s = 0; s < 2; s++) {
            const int kk = s * 8;
            uint32_t Ahf[2][4], Alf[2][4];
#pragma unroll
            for (int ma = 0; ma < 2; ma++) {
                const int r = wm * 32 + ma * 16 + tr;
                Ahf[ma][0] = __float_as_uint(Ph[kk + tc][r]);
                Ahf[ma][1] = __float_as_uint(Ph[kk + tc][r + 8]);
                Ahf[ma][2] = __float_as_uint(Ph[kk + tc + 4][r]);
                Ahf[ma][3] = __float_as_uint(Ph[kk + tc + 4][r + 8]);
                Alf[ma][0] = __float_as_uint(Pl[kk + tc][r]);
                Alf[ma][1] = __float_as_uint(Pl[kk + tc][r + 8]);
                Alf[ma][2] = __float_as_uint(Pl[kk + tc + 4][r]);
                Alf[ma][3] = __float_as_uint(Pl[kk + tc + 4][r + 8]);
            }
            uint32_t Bhf[4][2], Blf[4][2];
#pragma unroll
            for (int na = 0; na < 4; na++) {
                const int n = wn * 32 + na * 8 + tr;
                Bhf[na][0] = __float_as_uint(Vh[kk + tc][n]);
                Bhf[na][1] = __float_as_uint(Vh[kk + tc + 4][n]);
                Blf[na][0] = __float_as_uint(Vl[kk + tc][n]);
                Blf[na][1] = __float_as_uint(Vl[kk + tc + 4][n]);
            }
#pragma unroll
            for (int ma = 0; ma < 2; ma++)
#pragma unroll
                for (int na = 0; na < 4; na++) {
                    mma8(acc[ma][na], Ahf[ma], Bhf[na]);
                    mma8(acc[ma][na], Ahf[ma], Blf[na]);
                    mma8(acc[ma][na], Alf[ma], Bhf[na]);
                }
        }
    }
#pragma unroll
    for (int ma = 0; ma < 2; ma++) {
        const int rA = i0 + wm * 32 + ma * 16 + tr;
#pragma unroll
        for (int na = 0; na < 4; na++) {
            const int col = h * 64 + wn * 32 + na * 8 + 2 * tc;
            *(float2*)(out + (size_t)(b * Nn + rA) * Dd + col) =
                make_float2(acc[ma][na][0], acc[ma][na][1]);
            *(float2*)(out + (size_t)(b * Nn + rA + 8) * Dd + col) =
                make_float2(acc[ma][na][2], acc[ma][na][3]);
        }
    }
}

// ---------------- launch ----------------
extern "C" void kernel_launch(void* const* d_in, const int* in_sizes, int n_in,
                              void* d_out, int out_size)
{
    const float* x     = (const float*)d_in[0];
    const float* v     = (const float*)d_in[1];
    const float* Atopo = (const float*)d_in[2];
    const float* W     = (const float*)d_in[3];
    const float* bias  = (const float*)d_in[4];
    const float* tau   = (const float*)d_in[5];
    const float* gamma = (const float*)d_in[6];
    float* out = (float*)d_out;

    float *p_qkvx, *p_qkvv;
    unsigned *p_Ab, *p_A2b, *p_A3b;
    cudaGetSymbolAddress((void**)&p_qkvx, sc_qkvx);
    cudaGetSymbolAddress((void**)&p_qkvv, sc_qkvv);
    cudaGetSymbolAddress((void**)&p_Ab, sc_Ab);
    cudaGetSymbolAddress((void**)&p_A2b, sc_A2b);
    cudaGetSymbolAddress((void**)&p_A3b, sc_A3b);

    qkv_kernel<<<dim3(12, 32), 256>>>(x, W, bias, p_qkvx, 1536);
    qkv_kernel<<<dim3(8, 32), 256>>>(v, W, bias, p_qkvv, 1024);
    pre_kernel<<<4096, 256>>>(tau);
    pack_kernel<<<4096, 256>>>(Atopo);
    reach_kernel<<<128, 256>>>(p_Ab, p_Ab, p_A2b);
    reach_kernel<<<128, 256>>>(p_A2b, p_Ab, p_A3b);
    code_kernel<<<4096, 256>>>();
    score_mma_kernel<<<dim3(32, 8, 8), 256>>>(tau, gamma, out);
    softmax_kernel<<<32768, 256>>>(out + (size_t)Z_ELEMS);
    z_mma_kernel<<<dim3(32, 8), 256>>>(out + (size_t)Z_ELEMS, out);
}